// round 2
// baseline (speedup 1.0000x reference)
#include <cuda_runtime.h>
#include <math.h>

#define TLEN   4096
#define NBATCH 8
#define TOK    (NBATCH*TLEN)   // 32768 tokens
#define CH     256
#define CH2    512
#define SPECT  640
#define KCONV  768             // 3 taps * 256
#define KTOT   1408            // 768 + 640
#define NLAYERS 12

// Scratch (alloc-free rule: __device__ globals)
__device__ float g_started[TOK*CH];
__device__ float g_activated[TOK*CH];
__device__ float g_skip[TOK*CH];

// ---------------------------------------------------------------------------
// started = audio @ w_start + b_start ; skip = 0
// ---------------------------------------------------------------------------
__global__ void start_kernel(const float* __restrict__ audio,
                             const float* __restrict__ w_start,
                             const float* __restrict__ b_start)
{
    int idx = blockIdx.x * blockDim.x + threadIdx.x;   // over TOK*CH
    if (idx >= TOK*CH) return;
    int token = idx >> 8;
    int c     = idx & 255;
    const float* a = audio + token*4;
    float v = b_start[c];
    v += a[0]*w_start[0*CH + c];
    v += a[1]*w_start[1*CH + c];
    v += a[2]*w_start[2*CH + c];
    v += a[3]*w_start[3*CH + c];
    g_started[idx] = v;
    g_skip[idx] = 0.f;
}

// ---------------------------------------------------------------------------
// Gate kernel: for a tile of 64 tokens x 64 activated channels, compute
//   acts[:, c]     (tanh half)  and acts[:, c+256] (sigmoid half)
// acts = sum_{tap} started[t+(tap-1)*dil] @ w_in[tap] + spect[t] @ w_cond + b
// then g_activated = tanh * sigmoid.
// GEMM: M=64, Ncols=128 (paired halves), K=1408.
// ---------------------------------------------------------------------------
__global__ void __launch_bounds__(256) gate_kernel(
    const float* __restrict__ spect,
    const float* __restrict__ w_in,    // [3,256,512] (this layer)
    const float* __restrict__ b_in,    // [512]
    const float* __restrict__ w_cond,  // [640,512]
    const float* __restrict__ b_cond,  // [512]
    int dil)
{
    const int KT = 16;
    __shared__ float As[KT][65];     // [k][m], padded vs. bank conflicts
    __shared__ float Bs[KT][128];    // [k][c], c<64 tanh cols, c>=64 sig cols

    int tid = threadIdx.x;
    int m0  = blockIdx.x * 64;       // token tile base
    int n0  = blockIdx.y * 64;       // activated-channel tile base (0..255)

    int tm = tid >> 4;               // 0..15 -> rows tm*4..tm*4+3
    int tn = tid & 15;               // 0..15 -> cols tn*4..tn*4+3 (x2 halves)

    float acc[4][8];
    #pragma unroll
    for (int i = 0; i < 4; i++)
        #pragma unroll
        for (int j = 0; j < 8; j++) acc[i][j] = 0.f;

    for (int kt = 0; kt < KTOT; kt += KT) {
        // ---- load A tile (16 x 64): A[m][k] = concat-K input for token m ----
        #pragma unroll
        for (int r = 0; r < 4; r++) {
            int idx = tid + r*256;
            int k = idx & 15, m = idx >> 4;
            int kk = kt + k;
            int token = m0 + m;
            float v;
            if (kk < KCONV) {
                int tap = kk >> 8;          // 0,1,2
                int ch  = kk & 255;
                int b   = token >> 12;
                int t   = token & (TLEN-1);
                int ts  = t + (tap - 1) * dil;
                v = ((unsigned)ts < (unsigned)TLEN)
                        ? g_started[(((b << 12) + ts) << 8) + ch] : 0.f;
            } else {
                v = spect[token*SPECT + (kk - KCONV)];
            }
            As[k][m] = v;
        }
        // ---- load B tile (16 x 128) ----
        #pragma unroll
        for (int r = 0; r < 8; r++) {
            int idx = tid + r*256;
            int k = idx >> 7, c = idx & 127;
            int kk = kt + k;
            int col = (c < 64) ? (n0 + c) : (n0 + 256 + (c - 64));
            const float* row = (kk < KCONV) ? (w_in + (size_t)kk * CH2)
                                            : (w_cond + (size_t)(kk - KCONV) * CH2);
            Bs[k][c] = row[col];
        }
        __syncthreads();
        #pragma unroll
        for (int k = 0; k < KT; k++) {
            float a[4];
            #pragma unroll
            for (int i = 0; i < 4; i++) a[i] = As[k][tm*4 + i];
            float4 bv0 = *(const float4*)&Bs[k][tn*4];
            float4 bv1 = *(const float4*)&Bs[k][64 + tn*4];
            float bb[8] = {bv0.x, bv0.y, bv0.z, bv0.w,
                           bv1.x, bv1.y, bv1.z, bv1.w};
            #pragma unroll
            for (int i = 0; i < 4; i++)
                #pragma unroll
                for (int j = 0; j < 8; j++)
                    acc[i][j] += a[i] * bb[j];
        }
        __syncthreads();
    }

    // ---- epilogue: gated activation ----
    int colT = n0 + tn*4;
    float biasT[4], biasS[4];
    #pragma unroll
    for (int j = 0; j < 4; j++) {
        biasT[j] = b_in[colT + j]       + b_cond[colT + j];
        biasS[j] = b_in[colT + 256 + j] + b_cond[colT + 256 + j];
    }
    #pragma unroll
    for (int i = 0; i < 4; i++) {
        int token = m0 + tm*4 + i;
        float* outp = g_activated + (size_t)token*CH + colT;
        #pragma unroll
        for (int j = 0; j < 4; j++) {
            float at  = acc[i][j]     + biasT[j];
            float as  = acc[i][4 + j] + biasS[j];
            float sig = 1.f / (1.f + __expf(-as));
            outp[j] = tanhf(at) * sig;
        }
    }
}

// ---------------------------------------------------------------------------
// Residual kernel: rs = activated @ w + bias
//   last==0 (Nout=512): started[:, col] += rs[:, col<256]; skip += rs[:, 256:]
//   last==1 (Nout=256): skip += rs
// ---------------------------------------------------------------------------
__global__ void __launch_bounds__(256) res_kernel(
    const float* __restrict__ w,      // [256, nout]
    const float* __restrict__ bias,   // [nout]
    int nout, int last)
{
    const int KT = 16;
    __shared__ float As[KT][65];
    __shared__ float Bs[KT][64];

    int tid = threadIdx.x;
    int m0  = blockIdx.x * 64;
    int n0  = blockIdx.y * 64;
    int tm  = tid >> 4, tn = tid & 15;

    float acc[4][4];
    #pragma unroll
    for (int i = 0; i < 4; i++)
        #pragma unroll
        for (int j = 0; j < 4; j++) acc[i][j] = 0.f;

    for (int kt = 0; kt < CH; kt += KT) {
        #pragma unroll
        for (int r = 0; r < 4; r++) {
            int idx = tid + r*256;
            int k = idx & 15, m = idx >> 4;
            As[k][m] = g_activated[(size_t)(m0 + m)*CH + kt + k];
        }
        #pragma unroll
        for (int r = 0; r < 4; r++) {
            int idx = tid + r*256;
            int k = idx >> 6, c = idx & 63;
            Bs[k][c] = w[(size_t)(kt + k)*nout + n0 + c];
        }
        __syncthreads();
        #pragma unroll
        for (int k = 0; k < KT; k++) {
            float a[4];
            #pragma unroll
            for (int i = 0; i < 4; i++) a[i] = As[k][tm*4 + i];
            float4 bv = *(const float4*)&Bs[k][tn*4];
            float bb[4] = {bv.x, bv.y, bv.z, bv.w};
            #pragma unroll
            for (int i = 0; i < 4; i++)
                #pragma unroll
                for (int j = 0; j < 4; j++)
                    acc[i][j] += a[i] * bb[j];
        }
        __syncthreads();
    }

    int col = n0 + tn*4;
    #pragma unroll
    for (int i = 0; i < 4; i++) {
        int token = m0 + tm*4 + i;
        #pragma unroll
        for (int j = 0; j < 4; j++) {
            float v = acc[i][j] + bias[col + j];
            if (last) {
                g_skip[(size_t)token*CH + col + j] += v;
            } else if (col < 256) {
                g_started[(size_t)token*CH + col + j] += v;
            } else {
                g_skip[(size_t)token*CH + col - 256 + j] += v;
            }
        }
    }
}

// ---------------------------------------------------------------------------
// out = skip @ w_end + b_end      (K=256, N=8)
// ---------------------------------------------------------------------------
__global__ void end_kernel(const float* __restrict__ w_end,
                           const float* __restrict__ b_end,
                           float* __restrict__ out)
{
    int idx = blockIdx.x * blockDim.x + threadIdx.x;  // over TOK*8
    if (idx >= TOK*8) return;
    int token = idx >> 3;
    int j     = idx & 7;
    const float* s = g_skip + (size_t)token*CH;
    float v = b_end[j];
    #pragma unroll 8
    for (int c = 0; c < CH; c++)
        v += s[c] * w_end[c*8 + j];
    out[idx] = v;
}

// ---------------------------------------------------------------------------
extern "C" void kernel_launch(void* const* d_in, const int* in_sizes, int n_in,
                              void* d_out, int out_size)
{
    const float* audio      = (const float*)d_in[0];
    const float* spect      = (const float*)d_in[1];
    const float* w_start    = (const float*)d_in[2];
    const float* b_start    = (const float*)d_in[3];
    const float* w_in       = (const float*)d_in[4];
    const float* b_in       = (const float*)d_in[5];
    const float* w_cond     = (const float*)d_in[6];
    const float* b_cond     = (const float*)d_in[7];
    const float* w_res      = (const float*)d_in[8];
    const float* b_res      = (const float*)d_in[9];
    const float* w_res_last = (const float*)d_in[10];
    const float* b_res_last = (const float*)d_in[11];
    const float* w_end      = (const float*)d_in[12];
    const float* b_end      = (const float*)d_in[13];
    float* out = (float*)d_out;

    start_kernel<<<(TOK*CH + 255)/256, 256>>>(audio, w_start, b_start);

    for (int l = 0; l < NLAYERS; l++) {
        gate_kernel<<<dim3(TOK/64, 4), 256>>>(
            spect,
            w_in   + (size_t)l * 3 * CH * CH2,
            b_in   + (size_t)l * CH2,
            w_cond + (size_t)l * SPECT * CH2,
            b_cond + (size_t)l * CH2,
            1 << l);
        if (l < NLAYERS - 1) {
            res_kernel<<<dim3(TOK/64, 8), 256>>>(
                w_res + (size_t)l * CH * CH2,
                b_res + (size_t)l * CH2,
                CH2, 0);
        } else {
            res_kernel<<<dim3(TOK/64, 4), 256>>>(
                w_res_last, b_res_last, CH, 1);
        }
    }

    end_kernel<<<(TOK*8 + 255)/256, 256>>>(w_end, b_end, out);
}

// round 3
// speedup vs baseline: 2.8835x; 2.8835x over previous
#include <cuda_runtime.h>
#include <cuda_bf16.h>
#include <math.h>

#define TLEN   4096
#define TOK    32768
#define CH     256
#define CH2    512
#define SPECT  640
#define KCONV  768
#define KTOT   1408
#define NLAYERS 12
#define SA     24          // smem k-stride (elems): conflict-free for frag loads

typedef unsigned int u32;

// ------------------------- device scratch (alloc-free rule) -----------------
__device__ float g_started[TOK*CH];
__device__ float g_skip[TOK*CH];
__device__ __nv_bfloat16 g_sh[TOK*CH],   g_sl[TOK*CH];     // started hi/lo
__device__ __nv_bfloat16 g_ah[TOK*CH],   g_al[TOK*CH];     // activated hi/lo
__device__ __nv_bfloat16 g_xh[TOK*SPECT],g_xl[TOK*SPECT];  // spect hi/lo
__device__ __nv_bfloat16 g_bgh[NLAYERS*CH2*KTOT], g_bgl[NLAYERS*CH2*KTOT]; // gate W^T [l][n][k]
__device__ __nv_bfloat16 g_brh[(NLAYERS-1)*CH2*CH], g_brl[(NLAYERS-1)*CH2*CH]; // res W^T
__device__ __nv_bfloat16 g_blh[CH*CH], g_bll[CH*CH];       // last res W^T

__device__ __forceinline__ void split2(float v, __nv_bfloat16& h, __nv_bfloat16& l){
    h = __float2bfloat16(v);
    l = __float2bfloat16(v - __bfloat162float(h));
}

__device__ __forceinline__ void mma_bf(float* c, const u32* a, const u32* b){
    asm volatile(
      "mma.sync.aligned.m16n8k16.row.col.f32.bf16.bf16.f32 "
      "{%0,%1,%2,%3}, {%4,%5,%6,%7}, {%8,%9}, {%0,%1,%2,%3};\n"
      : "+f"(c[0]), "+f"(c[1]), "+f"(c[2]), "+f"(c[3])
      : "r"(a[0]), "r"(a[1]), "r"(a[2]), "r"(a[3]), "r"(b[0]), "r"(b[1]));
}
__device__ __forceinline__ void cpa16(u32 dst, const void* src, u32 sz){
    asm volatile("cp.async.cg.shared.global [%0], [%1], 16, %2;\n"
                 :: "r"(dst), "l"(src), "r"(sz));
}
__device__ __forceinline__ void cpa_commit(){ asm volatile("cp.async.commit_group;\n"); }
__device__ __forceinline__ void cpa_wait(){ asm volatile("cp.async.wait_group 0;\n"); }

// ------------------------------ prep kernels --------------------------------
__global__ void prep_spect_kernel(const float* __restrict__ spect){
    int i = blockIdx.x*256 + threadIdx.x;
    if (i >= TOK*SPECT) return;
    split2(spect[i], g_xh[i], g_xl[i]);
}
__global__ void prep_gateB_kernel(const float* __restrict__ w_in,
                                  const float* __restrict__ w_cond){
    long i = (long)blockIdx.x*256 + threadIdx.x;
    if (i >= (long)NLAYERS*CH2*KTOT) return;
    int kk = (int)(i % KTOT);
    long r = i / KTOT;
    int n  = (int)(r % CH2);
    int l  = (int)(r / CH2);
    float v = (kk < KCONV) ? w_in[((size_t)l*KCONV + kk)*CH2 + n]
                           : w_cond[((size_t)l*SPECT + (kk-KCONV))*CH2 + n];
    split2(v, g_bgh[i], g_bgl[i]);
}
__global__ void prep_resB_kernel(const float* __restrict__ w_res,
                                 const float* __restrict__ w_res_last){
    int i = blockIdx.x*256 + threadIdx.x;
    const int NRES = (NLAYERS-1)*CH2*CH;
    if (i < NRES){
        int k = i % CH;
        int r = i / CH;
        int n = r % CH2;
        int l = r / CH2;
        float v = w_res[((size_t)l*CH + k)*CH2 + n];
        split2(v, g_brh[i], g_brl[i]);
    } else if (i < NRES + CH*CH){
        int j = i - NRES;
        int k = j % CH;
        int n = j / CH;
        float v = w_res_last[(size_t)k*CH + n];
        split2(v, g_blh[j], g_bll[j]);
    }
}

// ------------------------------ start kernel --------------------------------
__global__ void start_kernel(const float* __restrict__ audio,
                             const float* __restrict__ w_start,
                             const float* __restrict__ b_start)
{
    int idx = blockIdx.x*256 + threadIdx.x;
    if (idx >= TOK*CH) return;
    int token = idx >> 8;
    int c     = idx & 255;
    const float* a = audio + token*4;
    float v = b_start[c];
    v += a[0]*w_start[0*CH + c];
    v += a[1]*w_start[1*CH + c];
    v += a[2]*w_start[2*CH + c];
    v += a[3]*w_start[3*CH + c];
    g_started[idx] = v;
    split2(v, g_sh[idx], g_sl[idx]);
    g_skip[idx] = 0.f;
}

// ------------------------------ gate kernel ---------------------------------
// Block: 128 tokens x (64 tanh cols + 64 sig cols). K=1408 = 88 chunks of 16.
// bf16 split-2: acc += Ahi*Bhi + Alo*Bhi + Ahi*Blo.
__global__ void __launch_bounds__(256,2) gate_kernel(
    const float* __restrict__ b_in, const float* __restrict__ b_cond,
    int layer, int dil)
{
    __shared__ __nv_bfloat16 sm[2][4][128*SA]; // [buf][Ah,Al,Bh,Bl][row*SA+k]

    int tid = threadIdx.x;
    int m0 = blockIdx.x*128;
    int n0 = blockIdx.y*64;          // tanh column base (0,64,128,192)
    int warp = tid>>5, lane = tid&31;
    int wm = warp>>1, wn = warp&1;
    int g = lane>>2,  tig = lane&3;

    // tile-load mapping: 2 threads per row, each 16B (8 bf16) per plane
    int lrow = tid>>1, lhalf = tid&1;
    int token = m0 + lrow;
    int bb = token>>12, tt = token&(TLEN-1);
    int cw = lrow>>6, cc2 = lrow&63;
    int ncol = (cc2<32) ? (n0 + cw*32 + cc2) : (256 + n0 + cw*32 + (cc2-32));
    const __nv_bfloat16* browh = g_bgh + ((size_t)layer*CH2 + ncol)*KTOT;
    const __nv_bfloat16* browl = g_bgl + ((size_t)layer*CH2 + ncol)*KTOT;
    const __nv_bfloat16* arow_xh = g_xh + (size_t)token*SPECT;
    const __nv_bfloat16* arow_xl = g_xl + (size_t)token*SPECT;

    u32 sbase = (u32)__cvta_generic_to_shared(&sm[0][0][0]);
    u32 doff  = (u32)(lrow*SA + lhalf*8)*2;
    const u32 PL = 128*SA*2; // plane bytes

    auto load_tiles = [&](int kc, int buf){
        u32 pb = sbase + (u32)buf*4u*PL;
        const __nv_bfloat16 *ah, *al; u32 sz;
        if (kc < 48){
            int tap = kc>>4;
            int ch  = ((kc&15)<<4) + lhalf*8;
            int ts  = tt + (tap-1)*dil;
            bool ok = ((unsigned)ts < (unsigned)TLEN);
            int tok2 = (bb<<12) + (ok ? ts : 0);
            ah = g_sh + ((size_t)tok2<<8) + ch;
            al = g_sl + ((size_t)tok2<<8) + ch;
            sz = ok ? 16u : 0u;
        } else {
            int koff = ((kc-48)<<4) + lhalf*8;
            ah = arow_xh + koff;
            al = arow_xl + koff;
            sz = 16u;
        }
        cpa16(pb        + doff, ah, sz);
        cpa16(pb + PL   + doff, al, sz);
        int kb = (kc<<4) + lhalf*8;
        cpa16(pb + 2*PL + doff, browh + kb, 16u);
        cpa16(pb + 3*PL + doff, browl + kb, 16u);
        cpa_commit();
    };

    float acc[2][8][4];
    #pragma unroll
    for (int mt=0;mt<2;mt++)
        #pragma unroll
        for (int j=0;j<8;j++)
            #pragma unroll
            for (int r2=0;r2<4;r2++) acc[mt][j][r2]=0.f;

    load_tiles(0,0);
    const int NKC = KTOT/16;
    for (int kc=0; kc<NKC; kc++){
        cpa_wait(); __syncthreads();
        if (kc+1 < NKC) load_tiles(kc+1, (kc+1)&1);
        int buf = kc&1;

        u32 fa[2][2][4]; // [limb][mtile][reg]
        #pragma unroll
        for (int mt=0; mt<2; mt++){
            int r0 = (wm*32 + mt*16 + g)*SA + 2*tig;
            const __nv_bfloat16* ph = &sm[buf][0][r0];
            fa[0][mt][0] = *(const u32*)(ph);
            fa[0][mt][1] = *(const u32*)(ph + 8*SA);
            fa[0][mt][2] = *(const u32*)(ph + 8);
            fa[0][mt][3] = *(const u32*)(ph + 8*SA + 8);
            const __nv_bfloat16* pl = &sm[buf][1][r0];
            fa[1][mt][0] = *(const u32*)(pl);
            fa[1][mt][1] = *(const u32*)(pl + 8*SA);
            fa[1][mt][2] = *(const u32*)(pl + 8);
            fa[1][mt][3] = *(const u32*)(pl + 8*SA + 8);
        }
        #pragma unroll
        for (int j=0; j<8; j++){
            int cr = (wn*64 + j*8 + g)*SA + 2*tig;
            const __nv_bfloat16* pbh = &sm[buf][2][cr];
            u32 bh[2] = { *(const u32*)pbh, *(const u32*)(pbh+8) };
            const __nv_bfloat16* pbl = &sm[buf][3][cr];
            u32 bl[2] = { *(const u32*)pbl, *(const u32*)(pbl+8) };
            mma_bf(acc[0][j], fa[0][0], bh);
            mma_bf(acc[1][j], fa[0][1], bh);
            mma_bf(acc[0][j], fa[1][0], bh);
            mma_bf(acc[1][j], fa[1][1], bh);
            mma_bf(acc[0][j], fa[0][0], bl);
            mma_bf(acc[1][j], fa[0][1], bl);
        }
    }

    // epilogue: acc[mt][j] = tanh half, acc[mt][j+4] = matching sigmoid half
    #pragma unroll
    for (int mt=0; mt<2; mt++){
        #pragma unroll
        for (int j=0; j<4; j++){
            int ct = n0 + wn*32 + j*8 + 2*tig;
            float bT0 = b_in[ct]     + b_cond[ct];
            float bT1 = b_in[ct+1]   + b_cond[ct+1];
            float bS0 = b_in[ct+256] + b_cond[ct+256];
            float bS1 = b_in[ct+257] + b_cond[ct+257];
            #pragma unroll
            for (int h=0; h<2; h++){
                int row = m0 + wm*32 + mt*16 + g + h*8;
                float t0 = acc[mt][j][h*2+0] + bT0;
                float t1 = acc[mt][j][h*2+1] + bT1;
                float s0 = acc[mt][j+4][h*2+0] + bS0;
                float s1 = acc[mt][j+4][h*2+1] + bS1;
                float v0 = tanhf(t0) * (1.f/(1.f+__expf(-s0)));
                float v1 = tanhf(t1) * (1.f/(1.f+__expf(-s1)));
                __nv_bfloat16 h0,l0,h1,l1;
                split2(v0,h0,l0); split2(v1,h1,l1);
                size_t o = (size_t)row*CH + ct;
                __nv_bfloat162 vh; vh.x=h0; vh.y=h1;
                __nv_bfloat162 vl; vl.x=l0; vl.y=l1;
                *(__nv_bfloat162*)&g_ah[o] = vh;
                *(__nv_bfloat162*)&g_al[o] = vl;
            }
        }
    }
}

// ------------------------------ res kernel ----------------------------------
// rs = activated @ w + bias; cols<256 -> started update (+ re-split),
// cols>=256 -> skip accumulation. last: all 256 cols -> skip.
__global__ void __launch_bounds__(256,2) res_kernel(
    const float* __restrict__ bias, int layer, int last)
{
    __shared__ __nv_bfloat16 sm[2][4][128*SA];

    int tid = threadIdx.x;
    int m0 = blockIdx.x*128;
    int n0 = blockIdx.y*128;
    int warp = tid>>5, lane = tid&31;
    int wm = warp>>1, wn = warp&1;
    int g = lane>>2,  tig = lane&3;

    int lrow = tid>>1, lhalf = tid&1;
    int token = m0 + lrow;
    int ncol = n0 + lrow;
    const __nv_bfloat16* browh = last ? (g_blh + (size_t)ncol*CH)
                                      : (g_brh + ((size_t)layer*CH2 + ncol)*CH);
    const __nv_bfloat16* browl = last ? (g_bll + (size_t)ncol*CH)
                                      : (g_brl + ((size_t)layer*CH2 + ncol)*CH);
    const __nv_bfloat16* arh = g_ah + (size_t)token*CH;
    const __nv_bfloat16* arl = g_al + (size_t)token*CH;

    u32 sbase = (u32)__cvta_generic_to_shared(&sm[0][0][0]);
    u32 doff  = (u32)(lrow*SA + lhalf*8)*2;
    const u32 PL = 128*SA*2;

    auto load_tiles = [&](int kc, int buf){
        u32 pb = sbase + (u32)buf*4u*PL;
        int kb = (kc<<4) + lhalf*8;
        cpa16(pb        + doff, arh + kb, 16u);
        cpa16(pb + PL   + doff, arl + kb, 16u);
        cpa16(pb + 2*PL + doff, browh + kb, 16u);
        cpa16(pb + 3*PL + doff, browl + kb, 16u);
        cpa_commit();
    };

    float acc[2][8][4];
    #pragma unroll
    for (int mt=0;mt<2;mt++)
        #pragma unroll
        for (int j=0;j<8;j++)
            #pragma unroll
            for (int r2=0;r2<4;r2++) acc[mt][j][r2]=0.f;

    load_tiles(0,0);
    const int NKC = CH/16;
    for (int kc=0; kc<NKC; kc++){
        cpa_wait(); __syncthreads();
        if (kc+1 < NKC) load_tiles(kc+1, (kc+1)&1);
        int buf = kc&1;

        u32 fa[2][2][4];
        #pragma unroll
        for (int mt=0; mt<2; mt++){
            int r0 = (wm*32 + mt*16 + g)*SA + 2*tig;
            const __nv_bfloat16* ph = &sm[buf][0][r0];
            fa[0][mt][0] = *(const u32*)(ph);
            fa[0][mt][1] = *(const u32*)(ph + 8*SA);
            fa[0][mt][2] = *(const u32*)(ph + 8);
            fa[0][mt][3] = *(const u32*)(ph + 8*SA + 8);
            const __nv_bfloat16* pl = &sm[buf][1][r0];
            fa[1][mt][0] = *(const u32*)(pl);
            fa[1][mt][1] = *(const u32*)(pl + 8*SA);
            fa[1][mt][2] = *(const u32*)(pl + 8);
            fa[1][mt][3] = *(const u32*)(pl + 8*SA + 8);
        }
        #pragma unroll
        for (int j=0; j<8; j++){
            int cr = (wn*64 + j*8 + g)*SA + 2*tig;
            const __nv_bfloat16* pbh = &sm[buf][2][cr];
            u32 bh[2] = { *(const u32*)pbh, *(const u32*)(pbh+8) };
            const __nv_bfloat16* pbl = &sm[buf][3][cr];
            u32 bl[2] = { *(const u32*)pbl, *(const u32*)(pbl+8) };
            mma_bf(acc[0][j], fa[0][0], bh);
            mma_bf(acc[1][j], fa[0][1], bh);
            mma_bf(acc[0][j], fa[1][0], bh);
            mma_bf(acc[1][j], fa[1][1], bh);
            mma_bf(acc[0][j], fa[0][0], bl);
            mma_bf(acc[1][j], fa[0][1], bl);
        }
    }

    #pragma unroll
    for (int mt=0; mt<2; mt++){
        #pragma unroll
        for (int j=0; j<8; j++){
            int col = n0 + wn*64 + j*8 + 2*tig;
            float b0v = bias[col], b1v = bias[col+1];
            #pragma unroll
            for (int h=0; h<2; h++){
                int row = m0 + wm*32 + mt*16 + g + h*8;
                float v0 = acc[mt][j][h*2+0] + b0v;
                float v1 = acc[mt][j][h*2+1] + b1v;
                if (last){
                    size_t o = (size_t)row*CH + col;
                    g_skip[o]   += v0;
                    g_skip[o+1] += v1;
                } else if (col < 256){
                    size_t o = (size_t)row*CH + col;
                    float s0 = g_started[o]   + v0;
                    float s1 = g_started[o+1] + v1;
                    g_started[o]   = s0;
                    g_started[o+1] = s1;
                    __nv_bfloat16 h0,l0,h1,l1;
                    split2(s0,h0,l0); split2(s1,h1,l1);
                    __nv_bfloat162 vh; vh.x=h0; vh.y=h1;
                    __nv_bfloat162 vl; vl.x=l0; vl.y=l1;
                    *(__nv_bfloat162*)&g_sh[o] = vh;
                    *(__nv_bfloat162*)&g_sl[o] = vl;
                } else {
                    size_t o = (size_t)row*CH + col - 256;
                    g_skip[o]   += v0;
                    g_skip[o+1] += v1;
                }
            }
        }
    }
}

// ------------------------------ end kernel ----------------------------------
__global__ void end_kernel(const float* __restrict__ w_end,
                           const float* __restrict__ b_end,
                           float* __restrict__ out)
{
    int idx = blockIdx.x*256 + threadIdx.x;
    if (idx >= TOK*8) return;
    int token = idx >> 3;
    int j     = idx & 7;
    const float* s = g_skip + (size_t)token*CH;
    float v = b_end[j];
    #pragma unroll 8
    for (int c = 0; c < CH; c++)
        v += s[c] * w_end[c*8 + j];
    out[idx] = v;
}

// ----------------------------------------------------------------------------
extern "C" void kernel_launch(void* const* d_in, const int* in_sizes, int n_in,
                              void* d_out, int out_size)
{
    const float* audio      = (const float*)d_in[0];
    const float* spect      = (const float*)d_in[1];
    const float* w_start    = (const float*)d_in[2];
    const float* b_start    = (const float*)d_in[3];
    const float* w_in       = (const float*)d_in[4];
    const float* b_in       = (const float*)d_in[5];
    const float* w_cond     = (const float*)d_in[6];
    const float* b_cond     = (const float*)d_in[7];
    const float* w_res      = (const float*)d_in[8];
    const float* b_res      = (const float*)d_in[9];
    const float* w_res_last = (const float*)d_in[10];
    const float* b_res_last = (const float*)d_in[11];
    const float* w_end      = (const float*)d_in[12];
    const float* b_end      = (const float*)d_in[13];
    float* out = (float*)d_out;

    prep_spect_kernel<<<(TOK*SPECT + 255)/256, 256>>>(spect);
    prep_gateB_kernel<<<(NLAYERS*CH2*KTOT + 255)/256, 256>>>(w_in, w_cond);
    prep_resB_kernel<<<((NLAYERS-1)*CH2*CH + CH*CH + 255)/256, 256>>>(w_res, w_res_last);
    start_kernel<<<(TOK*CH + 255)/256, 256>>>(audio, w_start, b_start);

    for (int l = 0; l < NLAYERS; l++) {
        gate_kernel<<<dim3(TOK/128, 4), 256>>>(
            b_in + (size_t)l*CH2, b_cond + (size_t)l*CH2, l, 1 << l);
        if (l < NLAYERS - 1) {
            res_kernel<<<dim3(TOK/128, 4), 256>>>(b_res + (size_t)l*CH2, l, 0);
        } else {
            res_kernel<<<dim3(TOK/128, 2), 256>>>(b_res_last, l, 1);
        }
    }

    end_kernel<<<(TOK*8 + 255)/256, 256>>>(w_end, b_end, out);
}